// round 14
// baseline (speedup 1.0000x reference)
#include <cuda_runtime.h>
#include <cuda_fp16.h>
#include <math.h>
#include <stdint.h>

#define M_TOT   16384
#define DM      1024
#define DFF_    4096
#define MB(x)   ((size_t)(x) * 1048576ull)

// ---------------- scratch (byte offsets) ----------------
#define Q_OFF     MB(0)
#define K_OFF     MB(64)
#define V_OFF     MB(128)
#define X1_OFF    MB(192)
#define HH_OFF    MB(256)
#define AH_OFF    MB(288)
#define GH_OFF    MB(320)     // ..MB(448)
#define KV_OFF    MB(448)
#define KVP_OFF   MB(449)
#define WQKV_OFF  MB(457)
#define WO2_OFF   MB(463)
#define W1_OFF    MB(465)
#define W2_OFF    MB(481)
#define SCR_TOT   MB(489)

__device__ __align__(1024) unsigned char g_scratch[SCR_TOT];

// ---------------- PTX helpers (non-'a' ISA only) ----------------
__device__ __forceinline__ uint32_t smem_u32(const void* p) {
    uint32_t a;
    asm("{ .reg .u64 t; cvta.to.shared.u64 t, %1; cvt.u32.u64 %0, t; }" : "=r"(a) : "l"(p));
    return a;
}
__device__ __forceinline__ void cp16(uint32_t dst, const void* src) {
    asm volatile("cp.async.cg.shared.global [%0], [%1], 16;" :: "r"(dst), "l"(src) : "memory");
}
#define CP_COMMIT() asm volatile("cp.async.commit_group;" ::: "memory")
#define CP_WAIT(n)  asm volatile("cp.async.wait_group %0;" :: "n"(n) : "memory")

__device__ __forceinline__ void ldm4(uint32_t* r, uint32_t addr) {
    asm volatile("ldmatrix.sync.aligned.m8n8.x4.shared.b16 {%0,%1,%2,%3}, [%4];"
        : "=r"(r[0]), "=r"(r[1]), "=r"(r[2]), "=r"(r[3]) : "r"(addr));
}
// fp16-accumulator MMA (2x rate vs f32 acc)
__device__ __forceinline__ void mma16816h(uint32_t* d, const uint32_t* a, const uint32_t* b) {
    asm volatile("mma.sync.aligned.m16n8k16.row.col.f16.f16.f16.f16 "
        "{%0,%1}, {%2,%3,%4,%5}, {%6,%7}, {%0,%1};"
        : "+r"(d[0]), "+r"(d[1])
        : "r"(a[0]), "r"(a[1]), "r"(a[2]), "r"(a[3]), "r"(b[0]), "r"(b[1]));
}
__device__ __forceinline__ uint32_t packh(float a, float b) {
    __half2 t = __floats2half2_rn(a, b);
    return *(uint32_t*)&t;
}

// smem tile geometry: K-chunk 64 fp16 = 128B data + 16B pad -> 144B rows
#define ROWB    144u
#define APIECE  18432u        // 128 rows * 144B
#define BPIECE  36864u        // 256 rows * 144B
#define STAGEB  55296u        // A + B
#define NSTAGE  3
#define SMEM_GEMM (NSTAGE * 55296)

// -------- weight transpose: W[K x N] fp32 -> fp16 [N x K] --------
__global__ void wsplit_k(const float* __restrict__ W,
                         __half* __restrict__ out, int K, int N)
{
    __shared__ float t[32][33];
    int tx = threadIdx.x, ty = threadIdx.y;
    int n0 = blockIdx.x * 32, k0 = blockIdx.y * 32;
    #pragma unroll
    for (int i = 0; i < 4; i++)
        t[ty + i * 8][tx] = W[(size_t)(k0 + ty + i * 8) * N + n0 + tx];
    __syncthreads();
    #pragma unroll
    for (int i = 0; i < 4; i++)
        out[(size_t)(n0 + ty + i * 8) * K + k0 + tx] = __float2half(t[tx][ty + i * 8]);
}

// packed variant for W1: interleave 8 gate cols / 8 lin cols per 16 dst rows
__global__ void wsplit_pack_k(const float* __restrict__ W,
                              __half* __restrict__ out, int K, int N)
{
    __shared__ float t[32][33];
    int tx = threadIdx.x, ty = threadIdx.y;
    int n0 = blockIdx.x * 32, k0 = blockIdx.y * 32;
    #pragma unroll
    for (int i = 0; i < 4; i++)
        t[ty + i * 8][tx] = W[(size_t)(k0 + ty + i * 8) * N + n0 + tx];
    __syncthreads();
    #pragma unroll
    for (int i = 0; i < 4; i++) {
        int n = n0 + ty + i * 8;
        int dr = (n < 4096) ? ((n >> 3) * 16 + (n & 7))
                            : (((n - 4096) >> 3) * 16 + 8 + (n & 7));
        out[(size_t)dr * K + k0 + tx] = __float2half(t[tx][ty + i * 8]);
    }
}

// ---------------- layernorm -> fp16 ----------------
__global__ __launch_bounds__(256) void ln_k(const float* __restrict__ x,
                                            const float* __restrict__ gamma,
                                            const float* __restrict__ beta,
                                            __half* __restrict__ hh)
{
    int row = blockIdx.x, tid = threadIdx.x;
    float4 v = ((const float4*)(x + (size_t)row * DM))[tid];
    float s  = v.x + v.y + v.z + v.w;
    float ss = v.x*v.x + v.y*v.y + v.z*v.z + v.w*v.w;
    #pragma unroll
    for (int o = 16; o; o >>= 1) {
        s  += __shfl_xor_sync(0xffffffffu, s,  o);
        ss += __shfl_xor_sync(0xffffffffu, ss, o);
    }
    __shared__ float shs[8], shss[8], smu, srs;
    int w = tid >> 5, lane = tid & 31;
    if (lane == 0) { shs[w] = s; shss[w] = ss; }
    __syncthreads();
    if (tid == 0) {
        float ts = 0.f, tss = 0.f;
        #pragma unroll
        for (int i = 0; i < 8; i++) { ts += shs[i]; tss += shss[i]; }
        float mu  = ts * (1.0f / DM);
        float var = tss * (1.0f / DM) - mu * mu;
        smu = mu; srs = rsqrtf(var + 1e-5f);
    }
    __syncthreads();
    float mu = smu, rs = srs;
    float4 g = ((const float4*)gamma)[tid];
    float4 b = ((const float4*)beta)[tid];
    __align__(8) __half hb[4];
    hb[0] = __float2half((v.x-mu)*rs*g.x + b.x);
    hb[1] = __float2half((v.y-mu)*rs*g.y + b.y);
    hb[2] = __float2half((v.z-mu)*rs*g.z + b.z);
    hb[3] = __float2half((v.w-mu)*rs*g.w + b.w);
    ((uint2*)(hh + (size_t)row * DM))[tid] = *(uint2*)hb;
}

// ---------------- mma.sync GEMM: tile 128x256x64, 256 thr, warp tile 64x64 -------
// fp16 accumulate per K-64 chunk, promoted to fp32 once per chunk.
// EPI: 0 = +bias, 2 = +bias +residual, 3 = geglu -> fp16, 4 = fused QKV route
template<int EPI>
__global__ __launch_bounds__(256) void gemm_mma(
    const __half* __restrict__ A, const __half* __restrict__ B,
    const float* __restrict__ b0, const float* __restrict__ b1,
    const float* __restrict__ b2, const float* __restrict__ Rres,
    float* __restrict__ C0, float* __restrict__ C1, float* __restrict__ C2,
    __half* __restrict__ Gout,
    int Kdim, int Nout)
{
    extern __shared__ unsigned char dsm[];
    const int tid = threadIdx.x, wid = tid >> 5, lane = tid & 31;
    const int m0 = blockIdx.y * 128, n0 = blockIdx.x * 256;
    const int warp_m = (wid >> 2) * 64, warp_n = (wid & 3) * 64;
    const uint32_t dbase = smem_u32(dsm);

    auto fill = [&](int stage, int chunk) {
        uint32_t sb = dbase + (uint32_t)stage * STAGEB;
        int k0 = chunk << 6;
        #pragma unroll
        for (int it = 0; it < 12; it++) {
            int idx = tid + it * 256;          // 0..3071
            if (idx < 1024) {
                int row = idx >> 3, c = idx & 7;
                cp16(sb + (uint32_t)row * ROWB + (uint32_t)c * 16u,
                     A + (size_t)(m0 + row) * Kdim + k0 + c * 8);
            } else {
                int l = idx - 1024;            // 0..2047
                int row = l >> 3, c = l & 7;
                cp16(sb + APIECE + (uint32_t)row * ROWB + (uint32_t)c * 16u,
                     B + (size_t)(n0 + row) * Kdim + k0 + c * 8);
            }
        }
    };

    float acc[4][8][4];
    #pragma unroll
    for (int i = 0; i < 4; i++)
        #pragma unroll
        for (int j = 0; j < 8; j++)
            #pragma unroll
            for (int t = 0; t < 4; t++) acc[i][j][t] = 0.f;

    const int nk = Kdim >> 6;
    fill(0, 0); CP_COMMIT();
    if (nk > 1) { fill(1, 1); CP_COMMIT(); }

    int stage = 0;
    for (int c = 0; c < nk; c++) {
        if (c + 1 < nk) CP_WAIT(1);
        else            CP_WAIT(0);
        __syncthreads();
        if (c + 2 < nk) {
            int fs = stage + 2; if (fs >= NSTAGE) fs -= NSTAGE;
            fill(fs, c + 2); CP_COMMIT();
        }

        uint32_t sb = dbase + (uint32_t)stage * STAGEB;
        uint32_t aoff = sb, boff = sb + APIECE;

        // fp16 chunk accumulators
        uint32_t hacc[4][8][2];
        #pragma unroll
        for (int i = 0; i < 4; i++)
            #pragma unroll
            for (int j = 0; j < 8; j++) { hacc[i][j][0] = 0u; hacc[i][j][1] = 0u; }

        #pragma unroll
        for (int ks = 0; ks < 4; ks++) {
            uint32_t af[4][4];
            {
                int arow = warp_m + (lane & 15);
                uint32_t acol = (uint32_t)(ks * 2 + (lane >> 4)) * 16u;
                #pragma unroll
                for (int mt = 0; mt < 4; mt++)
                    ldm4(af[mt], aoff + (uint32_t)(arow + mt * 16) * ROWB + acol);
            }
            int brow = warp_n + (lane & 7) + ((lane >> 4) * 8);
            uint32_t bcol = (uint32_t)(ks * 2 + ((lane >> 3) & 1)) * 16u;
            #pragma unroll
            for (int np = 0; np < 4; np++) {
                uint32_t r[4];
                ldm4(r, boff + (uint32_t)(brow + np * 16) * ROWB + bcol);
                uint32_t bb0[2] = { r[0], r[1] }, bb1[2] = { r[2], r[3] };
                #pragma unroll
                for (int mt = 0; mt < 4; mt++) {
                    mma16816h(hacc[mt][np * 2 + 0], af[mt], bb0);
                    mma16816h(hacc[mt][np * 2 + 1], af[mt], bb1);
                }
            }
        }
        // promote chunk to fp32
        #pragma unroll
        for (int mt = 0; mt < 4; mt++)
            #pragma unroll
            for (int nt = 0; nt < 8; nt++) {
                float2 f0 = __half22float2(*(__half2*)&hacc[mt][nt][0]);
                float2 f1 = __half22float2(*(__half2*)&hacc[mt][nt][1]);
                acc[mt][nt][0] += f0.x; acc[mt][nt][1] += f0.y;
                acc[mt][nt][2] += f1.x; acc[mt][nt][3] += f1.y;
            }
        if (++stage >= NSTAGE) stage = 0;
    }

    // ---------------- epilogue ----------------
    int gid = lane >> 2, tig = lane & 3;
    if (EPI == 3) {
        const float is2 = 0.70710678118654752f;
        #pragma unroll
        for (int mt = 0; mt < 4; mt++) {
            int r0 = m0 + warp_m + mt * 16 + gid;
            #pragma unroll
            for (int j = 0; j < 4; j++) {
                int rc = ((n0 + warp_n) >> 1) + j * 8 + tig * 2;
                float2 bg = *(const float2*)(b0 + rc);
                float2 bl = *(const float2*)(b0 + 4096 + rc);
                float gv[4] = { acc[mt][2*j][0] + bg.x, acc[mt][2*j][1] + bg.y,
                                acc[mt][2*j][2] + bg.x, acc[mt][2*j][3] + bg.y };
                float lv[4] = { acc[mt][2*j+1][0] + bl.x, acc[mt][2*j+1][1] + bl.y,
                                acc[mt][2*j+1][2] + bl.x, acc[mt][2*j+1][3] + bl.y };
                float o[4];
                #pragma unroll
                for (int t = 0; t < 4; t++)
                    o[t] = 0.5f * gv[t] * (1.f + erff(gv[t] * is2)) * lv[t];
                size_t o0 = (size_t)r0 * 4096 + rc;
                size_t o1 = (size_t)(r0 + 8) * 4096 + rc;
                *(uint32_t*)(Gout + o0) = packh(o[0], o[1]);
                *(uint32_t*)(Gout + o1) = packh(o[2], o[3]);
            }
        }
    } else if (EPI == 4) {
        #pragma unroll
        for (int mt = 0; mt < 4; mt++) {
            int r0 = m0 + warp_m + mt * 16 + gid;
            #pragma unroll
            for (int nt = 0; nt < 8; nt++) {
                int col = n0 + warp_n + nt * 8 + tig * 2;   // global in [0,3072)
                const float* bp; float* Cp; int cl; bool elu;
                if (col < 1024)      { bp = b0 + col;        Cp = C0; cl = col;        elu = true; }
                else if (col < 2048) { bp = b1 + col - 1024; Cp = C1; cl = col - 1024; elu = true; }
                else                 { bp = b2 + col - 2048; Cp = C2; cl = col - 2048; elu = false; }
                float2 bb = *(const float2*)bp;
                float v0 = acc[mt][nt][0] + bb.x, v1 = acc[mt][nt][1] + bb.y;
                float v2 = acc[mt][nt][2] + bb.x, v3 = acc[mt][nt][3] + bb.y;
                if (elu) {
                    v0 = (v0 > 0.f) ? (v0 + 1.f) : expf(v0);
                    v1 = (v1 > 0.f) ? (v1 + 1.f) : expf(v1);
                    v2 = (v2 > 0.f) ? (v2 + 1.f) : expf(v2);
                    v3 = (v3 > 0.f) ? (v3 + 1.f) : expf(v3);
                }
                *(float2*)(Cp + (size_t)r0 * 1024 + cl)       = make_float2(v0, v1);
                *(float2*)(Cp + (size_t)(r0 + 8) * 1024 + cl) = make_float2(v2, v3);
            }
        }
    } else {
        #pragma unroll
        for (int mt = 0; mt < 4; mt++) {
            int r0 = m0 + warp_m + mt * 16 + gid;
            #pragma unroll
            for (int nt = 0; nt < 8; nt++) {
                int col = n0 + warp_n + nt * 8 + tig * 2;
                float2 bb = *(const float2*)(b0 + col);
                float v0 = acc[mt][nt][0] + bb.x, v1 = acc[mt][nt][1] + bb.y;
                float v2 = acc[mt][nt][2] + bb.x, v3 = acc[mt][nt][3] + bb.y;
                size_t o0 = (size_t)r0 * Nout + col;
                size_t o1 = (size_t)(r0 + 8) * Nout + col;
                if (EPI == 2) {
                    float2 ra = *(const float2*)(Rres + o0);
                    float2 rb = *(const float2*)(Rres + o1);
                    v0 += ra.x; v1 += ra.y; v2 += rb.x; v3 += rb.y;
                }
                *(float2*)(C0 + o0) = make_float2(v0, v1);
                *(float2*)(C0 + o1) = make_float2(v2, v3);
            }
        }
    }
}

// ---------------- kv = K^T V per (b,h), split over S ----------------
__global__ __launch_bounds__(256) void kv_partial_k(const float* __restrict__ Kp,
                                                    const float* __restrict__ Vp,
                                                    float* __restrict__ kvp)
{
    int bh = blockIdx.x, spi = blockIdx.y;
    int b = bh >> 4, h = bh & 15;
    int tid = threadIdx.x;
    __shared__ float ks[32][64], vs[32][64];
    float acc[4][4] = {};
    int d0 = (tid >> 4) * 4, e0 = (tid & 15) * 4;
    size_t base = ((size_t)b * 4096) * DM + h * 64;
    for (int s0 = spi * 512; s0 < spi * 512 + 512; s0 += 32) {
        #pragma unroll
        for (int i = 0; i < 2; i++) {
            int f = tid + i * 256;
            int r = f >> 4, c = (f & 15) * 4;
            size_t off = base + (size_t)(s0 + r) * DM + c;
            *(float4*)&ks[r][c] = *(const float4*)(Kp + off);
            *(float4*)&vs[r][c] = *(const float4*)(Vp + off);
        }
        __syncthreads();
        #pragma unroll
        for (int ssm = 0; ssm < 32; ssm++) {
            float kd[4] = { ks[ssm][d0], ks[ssm][d0+1], ks[ssm][d0+2], ks[ssm][d0+3] };
            float ve[4] = { vs[ssm][e0], vs[ssm][e0+1], vs[ssm][e0+2], vs[ssm][e0+3] };
            #pragma unroll
            for (int i = 0; i < 4; i++)
                #pragma unroll
                for (int j = 0; j < 4; j++) acc[i][j] += kd[i] * ve[j];
        }
        __syncthreads();
    }
    float* outp = kvp + ((size_t)spi * 64 + bh) * 4096;
    #pragma unroll
    for (int i = 0; i < 4; i++)
        *(float4*)(outp + (d0 + i) * 64 + e0) = make_float4(acc[i][0], acc[i][1], acc[i][2], acc[i][3]);
}

__global__ __launch_bounds__(256) void kv_reduce_k(const float* __restrict__ kvp,
                                                   float* __restrict__ kv)
{
    int i = blockIdx.x * 256 + threadIdx.x;
    float s = 0.f;
    #pragma unroll
    for (int spi = 0; spi < 8; spi++) s += kvp[(size_t)spi * 262144 + i];
    kv[i] = s;
}

// ---------------- attn = q @ kv per (b,h), out -> fp16 ----------------
__global__ __launch_bounds__(256) void attn_k(const float* __restrict__ Q,
                                              const float* __restrict__ KV,
                                              __half* __restrict__ Oh)
{
    int bh = blockIdx.x, st = blockIdx.y;
    int b = bh >> 4, h = bh & 15;
    int tid = threadIdx.x;
    __shared__ float kvs[64][64], qs[64][68];
    const float* kvsrc = KV + (size_t)bh * 4096;
    #pragma unroll
    for (int i = 0; i < 4; i++) {
        int f = tid + i * 256;
        int r = f >> 4, c = (f & 15) * 4;
        *(float4*)&kvs[r][c] = *(const float4*)(kvsrc + r * 64 + c);
    }
    size_t qbase = ((size_t)b * 4096 + st * 64) * DM + h * 64;
    #pragma unroll
    for (int i = 0; i < 4; i++) {
        int f = tid + i * 256;
        int r = f >> 4, c = (f & 15) * 4;
        *(float4*)&qs[r][c] = *(const float4*)(Q + qbase + (size_t)r * DM + c);
    }
    __syncthreads();
    int r = tid >> 2, e0 = (tid & 3) * 16;
    float acc[16] = {};
    #pragma unroll 8
    for (int d = 0; d < 64; d++) {
        float qd = qs[r][d];
        #pragma unroll
        for (int j = 0; j < 16; j++) acc[j] += qd * kvs[d][e0 + j];
    }
    size_t obase = qbase + (size_t)r * DM + e0;
    #pragma unroll
    for (int j = 0; j < 16; j += 2)
        *(uint32_t*)(Oh + obase + j) = packh(acc[j], acc[j + 1]);
}

// ---------------- launch ----------------
extern "C" void kernel_launch(void* const* d_in, const int* in_sizes, int n_in,
                              void* d_out, int out_size)
{
    const float* x   = (const float*)d_in[0];
    const float* wq  = (const float*)d_in[1];
    const float* bq  = (const float*)d_in[2];
    const float* wk  = (const float*)d_in[3];
    const float* bk  = (const float*)d_in[4];
    const float* wv  = (const float*)d_in[5];
    const float* bv  = (const float*)d_in[6];
    const float* wo  = (const float*)d_in[7];
    const float* bo  = (const float*)d_in[8];
    const float* w1  = (const float*)d_in[9];
    const float* b1  = (const float*)d_in[10];
    const float* w2  = (const float*)d_in[11];
    const float* b2  = (const float*)d_in[12];
    const float* g1  = (const float*)d_in[13];
    const float* be1 = (const float*)d_in[14];
    const float* g2  = (const float*)d_in[15];
    const float* be2 = (const float*)d_in[16];
    float* out = (float*)d_out;

    void* sp = nullptr;
    cudaGetSymbolAddress(&sp, g_scratch);
    unsigned char* S = (unsigned char*)sp;
    float* Qb    = (float*)(S + Q_OFF);
    float* Kb    = (float*)(S + K_OFF);
    float* Vb    = (float*)(S + V_OFF);
    float* X1    = (float*)(S + X1_OFF);
    __half* HH   = (__half*)(S + HH_OFF);
    __half* AH   = (__half*)(S + AH_OFF);
    __half* GH   = (__half*)(S + GH_OFF);
    float* KVb   = (float*)(S + KV_OFF);
    float* KVP   = (float*)(S + KVP_OFF);
    __half* WQKV = (__half*)(S + WQKV_OFF);
    __half* WO2  = (__half*)(S + WO2_OFF);
    __half* W1_  = (__half*)(S + W1_OFF);
    __half* W2_  = (__half*)(S + W2_OFF);

    static bool attr_done = false;
    if (!attr_done) {
        cudaFuncSetAttribute(gemm_mma<0>, cudaFuncAttributeMaxDynamicSharedMemorySize, SMEM_GEMM);
        cudaFuncSetAttribute(gemm_mma<2>, cudaFuncAttributeMaxDynamicSharedMemorySize, SMEM_GEMM);
        cudaFuncSetAttribute(gemm_mma<3>, cudaFuncAttributeMaxDynamicSharedMemorySize, SMEM_GEMM);
        cudaFuncSetAttribute(gemm_mma<4>, cudaFuncAttributeMaxDynamicSharedMemorySize, SMEM_GEMM);
        attr_done = true;
    }

    dim3 wb(32, 8);
    wsplit_k<<<dim3(32, 32), wb>>>(wq, WQKV,               DM, DM);
    wsplit_k<<<dim3(32, 32), wb>>>(wk, WQKV + 1024 * 1024, DM, DM);
    wsplit_k<<<dim3(32, 32), wb>>>(wv, WQKV + 2048 * 1024, DM, DM);
    wsplit_k<<<dim3(32, 32), wb>>>(wo, WO2, DM, DM);
    wsplit_pack_k<<<dim3(256, 32), wb>>>(w1, W1_, DM, 2 * DFF_);
    wsplit_k<<<dim3(32, 128), wb>>>(w2, W2_, DFF_, DM);

    dim3 gQKV(12, 128), gN1024(4, 128), gFF1(32, 128);

    // LN1
    ln_k<<<M_TOT, 256>>>(x, g1, be1, HH);
    // fused q/k/v projection (elu+1 on q,k)
    gemm_mma<4><<<gQKV, 256, SMEM_GEMM>>>(HH, WQKV, bq, bk, bv, nullptr,
                                          Qb, Kb, Vb, nullptr, DM, 1024);
    // linear attention
    kv_partial_k<<<dim3(64, 8), 256>>>(Kb, Vb, KVP);
    kv_reduce_k<<<1024, 256>>>(KVP, KVb);
    attn_k<<<dim3(64, 64), 256>>>(Qb, KVb, AH);
    // out proj + residual(x)
    gemm_mma<2><<<gN1024, 256, SMEM_GEMM>>>(AH, WO2, bo, nullptr, nullptr, x,
                                            X1, nullptr, nullptr, nullptr, DM, DM);
    // LN2
    ln_k<<<M_TOT, 256>>>(X1, g2, be2, HH);
    // FF1 + fused GEGLU -> fp16
    gemm_mma<3><<<gFF1, 256, SMEM_GEMM>>>(HH, W1_, b1, nullptr, nullptr, nullptr,
                                          nullptr, nullptr, nullptr, GH, DM, DFF_);
    // FF2 + residual(X1)
    gemm_mma<2><<<gN1024, 256, SMEM_GEMM>>>(GH, W2_, b2, nullptr, nullptr, X1,
                                            out, nullptr, nullptr, nullptr, DFF_, DM);
}

// round 15
// speedup vs baseline: 1.0852x; 1.0852x over previous
#include <cuda_runtime.h>
#include <cuda_fp16.h>
#include <math.h>
#include <stdint.h>

#define M_TOT   16384
#define DM      1024
#define DFF_    4096
#define MB(x)   ((size_t)(x) * 1048576ull)

// ---------------- scratch (byte offsets) ----------------
// Q/K/V fp16 (32MB), X1 fp32 (64MB), HH/AH fp16 (32MB), GH fp16 (128MB)
#define Q_OFF     MB(0)
#define K_OFF     MB(32)
#define V_OFF     MB(64)
#define X1_OFF    MB(96)
#define HH_OFF    MB(160)
#define AH_OFF    MB(192)
#define GH_OFF    MB(224)     // ..MB(352)
#define KV_OFF    MB(352)
#define KVP_OFF   MB(353)
#define WQKV_OFF  MB(361)
#define WO2_OFF   MB(367)
#define W1_OFF    MB(369)
#define W2_OFF    MB(385)
#define SCR_TOT   MB(393)

__device__ __align__(1024) unsigned char g_scratch[SCR_TOT];

// ---------------- PTX helpers (non-'a' ISA only) ----------------
__device__ __forceinline__ uint32_t smem_u32(const void* p) {
    uint32_t a;
    asm("{ .reg .u64 t; cvta.to.shared.u64 t, %1; cvt.u32.u64 %0, t; }" : "=r"(a) : "l"(p));
    return a;
}
__device__ __forceinline__ void cp16(uint32_t dst, const void* src) {
    asm volatile("cp.async.cg.shared.global [%0], [%1], 16;" :: "r"(dst), "l"(src) : "memory");
}
#define CP_COMMIT() asm volatile("cp.async.commit_group;" ::: "memory")
#define CP_WAIT(n)  asm volatile("cp.async.wait_group %0;" :: "n"(n) : "memory")

__device__ __forceinline__ void ldm4(uint32_t* r, uint32_t addr) {
    asm volatile("ldmatrix.sync.aligned.m8n8.x4.shared.b16 {%0,%1,%2,%3}, [%4];"
        : "=r"(r[0]), "=r"(r[1]), "=r"(r[2]), "=r"(r[3]) : "r"(addr));
}
__device__ __forceinline__ void mma16816(float* c, const uint32_t* a, const uint32_t* b) {
    asm volatile("mma.sync.aligned.m16n8k16.row.col.f32.f16.f16.f32 "
        "{%0,%1,%2,%3}, {%4,%5,%6,%7}, {%8,%9}, {%0,%1,%2,%3};"
        : "+f"(c[0]), "+f"(c[1]), "+f"(c[2]), "+f"(c[3])
        : "r"(a[0]), "r"(a[1]), "r"(a[2]), "r"(a[3]), "r"(b[0]), "r"(b[1]));
}
__device__ __forceinline__ uint32_t packh(float a, float b) {
    __half2 t = __floats2half2_rn(a, b);
    return *(uint32_t*)&t;
}

// smem tile geometry: K-chunk 64 fp16 = 128B data + 16B pad -> 144B rows
#define ROWB    144u
#define NSTAGE  3
#define SMEM_G128 (NSTAGE * (128 * 144 + 256 * 144))   // 165888
#define SMEM_G64  (NSTAGE * ( 64 * 144 + 256 * 144))   // 138240

// -------- weight transpose: W[K x N] fp32 -> fp16 [N x K] --------
__global__ void wsplit_k(const float* __restrict__ W,
                         __half* __restrict__ out, int K, int N)
{
    __shared__ float t[32][33];
    int tx = threadIdx.x, ty = threadIdx.y;
    int n0 = blockIdx.x * 32, k0 = blockIdx.y * 32;
    #pragma unroll
    for (int i = 0; i < 4; i++)
        t[ty + i * 8][tx] = W[(size_t)(k0 + ty + i * 8) * N + n0 + tx];
    __syncthreads();
    #pragma unroll
    for (int i = 0; i < 4; i++)
        out[(size_t)(n0 + ty + i * 8) * K + k0 + tx] = __float2half(t[tx][ty + i * 8]);
}

// packed variant for W1: interleave 8 gate cols / 8 lin cols per 16 dst rows
__global__ void wsplit_pack_k(const float* __restrict__ W,
                              __half* __restrict__ out, int K, int N)
{
    __shared__ float t[32][33];
    int tx = threadIdx.x, ty = threadIdx.y;
    int n0 = blockIdx.x * 32, k0 = blockIdx.y * 32;
    #pragma unroll
    for (int i = 0; i < 4; i++)
        t[ty + i * 8][tx] = W[(size_t)(k0 + ty + i * 8) * N + n0 + tx];
    __syncthreads();
    #pragma unroll
    for (int i = 0; i < 4; i++) {
        int n = n0 + ty + i * 8;
        int dr = (n < 4096) ? ((n >> 3) * 16 + (n & 7))
                            : (((n - 4096) >> 3) * 16 + 8 + (n & 7));
        out[(size_t)dr * K + k0 + tx] = __float2half(t[tx][ty + i * 8]);
    }
}

// ---------------- layernorm -> fp16 ----------------
__global__ __launch_bounds__(256) void ln_k(const float* __restrict__ x,
                                            const float* __restrict__ gamma,
                                            const float* __restrict__ beta,
                                            __half* __restrict__ hh)
{
    int row = blockIdx.x, tid = threadIdx.x;
    float4 v = ((const float4*)(x + (size_t)row * DM))[tid];
    float s  = v.x + v.y + v.z + v.w;
    float ss = v.x*v.x + v.y*v.y + v.z*v.z + v.w*v.w;
    #pragma unroll
    for (int o = 16; o; o >>= 1) {
        s  += __shfl_xor_sync(0xffffffffu, s,  o);
        ss += __shfl_xor_sync(0xffffffffu, ss, o);
    }
    __shared__ float shs[8], shss[8], smu, srs;
    int w = tid >> 5, lane = tid & 31;
    if (lane == 0) { shs[w] = s; shss[w] = ss; }
    __syncthreads();
    if (tid == 0) {
        float ts = 0.f, tss = 0.f;
        #pragma unroll
        for (int i = 0; i < 8; i++) { ts += shs[i]; tss += shss[i]; }
        float mu  = ts * (1.0f / DM);
        float var = tss * (1.0f / DM) - mu * mu;
        smu = mu; srs = rsqrtf(var + 1e-5f);
    }
    __syncthreads();
    float mu = smu, rs = srs;
    float4 g = ((const float4*)gamma)[tid];
    float4 b = ((const float4*)beta)[tid];
    __align__(8) __half hb[4];
    hb[0] = __float2half((v.x-mu)*rs*g.x + b.x);
    hb[1] = __float2half((v.y-mu)*rs*g.y + b.y);
    hb[2] = __float2half((v.z-mu)*rs*g.z + b.z);
    hb[3] = __float2half((v.w-mu)*rs*g.w + b.w);
    ((uint2*)(hh + (size_t)row * DM))[tid] = *(uint2*)hb;
}

// ---------------- mma.sync GEMM: tile TMx256x64, 256 thr, 3-stage cp.async -------
// TM = 128 (warp tile 64x64) or 64 (warp tile 32x64; halves wave quantization for
// small-N GEMMs). C = A[MxK] @ (B[NxK])^T, f32 accum (proven rate roof).
// EPI: 2 = +bias +residual (fp32 out), 3 = geglu -> fp16, 4 = fused QKV -> fp16
template<int EPI, int TM>
__global__ __launch_bounds__(256) void gemm_mma(
    const __half* __restrict__ A, const __half* __restrict__ B,
    const float* __restrict__ b0, const float* __restrict__ b1,
    const float* __restrict__ b2, const float* __restrict__ Rres,
    float* __restrict__ C0,
    __half* __restrict__ H0, __half* __restrict__ H1, __half* __restrict__ H2,
    __half* __restrict__ Gout,
    int Kdim, int Nout)
{
    constexpr int MT = TM / 32;                 // m-subtiles per warp (16 rows each)
    constexpr uint32_t APIECE = (uint32_t)TM * 144u;
    constexpr uint32_t STG    = APIECE + 36864u;
    constexpr int AEL = TM * 8;                 // A cp16 ops per chunk
    constexpr int NIT = (AEL + 2048) / 256;

    extern __shared__ unsigned char dsm[];
    const int tid = threadIdx.x, wid = tid >> 5, lane = tid & 31;
    const int m0 = blockIdx.y * TM, n0 = blockIdx.x * 256;
    const int warp_m = (wid >> 2) * (TM / 2), warp_n = (wid & 3) * 64;
    const uint32_t dbase = smem_u32(dsm);

    auto fill = [&](int stage, int chunk) {
        uint32_t sb = dbase + (uint32_t)stage * STG;
        int k0 = chunk << 6;
        #pragma unroll
        for (int it = 0; it < NIT; it++) {
            int idx = tid + it * 256;
            if (idx < AEL) {
                int row = idx >> 3, c = idx & 7;
                cp16(sb + (uint32_t)row * ROWB + (uint32_t)c * 16u,
                     A + (size_t)(m0 + row) * Kdim + k0 + c * 8);
            } else {
                int l = idx - AEL;             // 0..2047
                int row = l >> 3, c = l & 7;
                cp16(sb + APIECE + (uint32_t)row * ROWB + (uint32_t)c * 16u,
                     B + (size_t)(n0 + row) * Kdim + k0 + c * 8);
            }
        }
    };

    float acc[MT][8][4];
    #pragma unroll
    for (int i = 0; i < MT; i++)
        #pragma unroll
        for (int j = 0; j < 8; j++)
            #pragma unroll
            for (int t = 0; t < 4; t++) acc[i][j][t] = 0.f;

    const int nk = Kdim >> 6;
    fill(0, 0); CP_COMMIT();
    if (nk > 1) { fill(1, 1); CP_COMMIT(); }

    int stage = 0;
    for (int c = 0; c < nk; c++) {
        if (c + 1 < nk) CP_WAIT(1);
        else            CP_WAIT(0);
        __syncthreads();
        if (c + 2 < nk) {
            int fs = stage + 2; if (fs >= NSTAGE) fs -= NSTAGE;
            fill(fs, c + 2); CP_COMMIT();
        }

        uint32_t sb = dbase + (uint32_t)stage * STG;
        uint32_t aoff = sb, boff = sb + APIECE;

        #pragma unroll
        for (int ks = 0; ks < 4; ks++) {
            uint32_t af[MT][4];
            {
                int arow = warp_m + (lane & 15);
                uint32_t acol = (uint32_t)(ks * 2 + (lane >> 4)) * 16u;
                #pragma unroll
                for (int mt = 0; mt < MT; mt++)
                    ldm4(af[mt], aoff + (uint32_t)(arow + mt * 16) * ROWB + acol);
            }
            int brow = warp_n + (lane & 7) + ((lane >> 4) * 8);
            uint32_t bcol = (uint32_t)(ks * 2 + ((lane >> 3) & 1)) * 16u;
            #pragma unroll
            for (int np = 0; np < 4; np++) {
                uint32_t r[4];
                ldm4(r, boff + (uint32_t)(brow + np * 16) * ROWB + bcol);
                uint32_t bb0[2] = { r[0], r[1] }, bb1[2] = { r[2], r[3] };
                #pragma unroll
                for (int mt = 0; mt < MT; mt++) {
                    mma16816(acc[mt][np * 2 + 0], af[mt], bb0);
                    mma16816(acc[mt][np * 2 + 1], af[mt], bb1);
                }
            }
        }
        if (++stage >= NSTAGE) stage = 0;
    }

    // ---------------- epilogue ----------------
    int gid = lane >> 2, tig = lane & 3;
    if (EPI == 3) {
        const float is2 = 0.70710678118654752f;
        #pragma unroll
        for (int mt = 0; mt < MT; mt++) {
            int r0 = m0 + warp_m + mt * 16 + gid;
            #pragma unroll
            for (int j = 0; j < 4; j++) {
                int rc = ((n0 + warp_n) >> 1) + j * 8 + tig * 2;
                float2 bg = *(const float2*)(b0 + rc);
                float2 bl = *(const float2*)(b0 + 4096 + rc);
                float gv[4] = { acc[mt][2*j][0] + bg.x, acc[mt][2*j][1] + bg.y,
                                acc[mt][2*j][2] + bg.x, acc[mt][2*j][3] + bg.y };
                float lv[4] = { acc[mt][2*j+1][0] + bl.x, acc[mt][2*j+1][1] + bl.y,
                                acc[mt][2*j+1][2] + bl.x, acc[mt][2*j+1][3] + bl.y };
                float o[4];
                #pragma unroll
                for (int t = 0; t < 4; t++)
                    o[t] = 0.5f * gv[t] * (1.f + erff(gv[t] * is2)) * lv[t];
                size_t o0 = (size_t)r0 * 4096 + rc;
                size_t o1 = (size_t)(r0 + 8) * 4096 + rc;
                *(uint32_t*)(Gout + o0) = packh(o[0], o[1]);
                *(uint32_t*)(Gout + o1) = packh(o[2], o[3]);
            }
        }
    } else if (EPI == 4) {
        #pragma unroll
        for (int mt = 0; mt < MT; mt++) {
            int r0 = m0 + warp_m + mt * 16 + gid;
            #pragma unroll
            for (int nt = 0; nt < 8; nt++) {
                int col = n0 + warp_n + nt * 8 + tig * 2;   // global in [0,3072)
                const float* bp; __half* Hp; int cl; bool elu;
                if (col < 1024)      { bp = b0 + col;        Hp = H0; cl = col;        elu = true; }
                else if (col < 2048) { bp = b1 + col - 1024; Hp = H1; cl = col - 1024; elu = true; }
                else                 { bp = b2 + col - 2048; Hp = H2; cl = col - 2048; elu = false; }
                float2 bb = *(const float2*)bp;
                float v0 = acc[mt][nt][0] + bb.x, v1 = acc[mt][nt][1] + bb.y;
                float v2 = acc[mt][nt][2] + bb.x, v3 = acc[mt][nt][3] + bb.y;
                if (elu) {
                    v0 = (v0 > 0.f) ? (v0 + 1.f) : expf(v0);
                    v1 = (v1 > 0.f) ? (v1 + 1.f) : expf(v1);
                    v2 = (v2 > 0.f) ? (v2 + 1.f) : expf(v2);
                    v3 = (v3 > 0.f) ? (v3 + 1.f) : expf(v3);
                }
                *(uint32_t*)(Hp + (size_t)r0 * 1024 + cl)       = packh(v0, v1);
                *(uint32_t*)(Hp + (size_t)(r0 + 8) * 1024 + cl) = packh(v2, v3);
            }
        }
    } else {  // EPI == 2
        #pragma unroll
        for (int mt = 0; mt < MT; mt++) {
            int r0 = m0 + warp_m + mt * 16 + gid;
            #pragma unroll
            for (int nt = 0; nt < 8; nt++) {
                int col = n0 + warp_n + nt * 8 + tig * 2;
                float2 bb = *(const float2*)(b0 + col);
                float v0 = acc[mt][nt][0] + bb.x, v1 = acc[mt][nt][1] + bb.y;
                float v2 = acc[mt][nt][2] + bb.x, v3 = acc[mt][nt][3] + bb.y;
                size_t o0 = (size_t)r0 * Nout + col;
                size_t o1 = (size_t)(r0 + 8) * Nout + col;
                float2 ra = *(const float2*)(Rres + o0);
                float2 rb = *(const float2*)(Rres + o1);
                v0 += ra.x; v1 += ra.y; v2 += rb.x; v3 += rb.y;
                *(float2*)(C0 + o0) = make_float2(v0, v1);
                *(float2*)(C0 + o1) = make_float2(v2, v3);
            }
        }
    }
}

// ---------------- kv = K^T V per (b,h), split over S (fp16 in) ----------------
__global__ __launch_bounds__(256) void kv_partial_k(const __half* __restrict__ Kp,
                                                    const __half* __restrict__ Vp,
                                                    float* __restrict__ kvp)
{
    int bh = blockIdx.x, spi = blockIdx.y;
    int b = bh >> 4, h = bh & 15;
    int tid = threadIdx.x;
    __shared__ float ks[32][64], vs[32][64];
    float acc[4][4] = {};
    int d0 = (tid >> 4) * 4, e0 = (tid & 15) * 4;
    size_t base = ((size_t)b * 4096) * DM + h * 64;
    for (int s0 = spi * 512; s0 < spi * 512 + 512; s0 += 32) {
        {
            int r = tid >> 3, c = (tid & 7) * 8;
            size_t off = base + (size_t)(s0 + r) * DM + c;
            uint4 uk = *(const uint4*)(Kp + off);
            uint4 uv = *(const uint4*)(Vp + off);
            __half2* hk = (__half2*)&uk;
            __half2* hv = (__half2*)&uv;
            #pragma unroll
            for (int t = 0; t < 4; t++) {
                float2 fk = __half22float2(hk[t]);
                float2 fv = __half22float2(hv[t]);
                ks[r][c + 2*t] = fk.x; ks[r][c + 2*t + 1] = fk.y;
                vs[r][c + 2*t] = fv.x; vs[r][c + 2*t + 1] = fv.y;
            }
        }
        __syncthreads();
        #pragma unroll
        for (int ssm = 0; ssm < 32; ssm++) {
            float kd[4] = { ks[ssm][d0], ks[ssm][d0+1], ks[ssm][d0+2], ks[ssm][d0+3] };
            float ve[4] = { vs[ssm][e0], vs[ssm][e0+1], vs[ssm][e0+2], vs[ssm][e0+3] };
            #pragma unroll
            for (int i = 0; i < 4; i++)
                #pragma unroll
                for (int j = 0; j < 4; j++) acc[i][j] += kd[i] * ve[j];
        }
        __syncthreads();
    }
    float* outp = kvp + ((size_t)spi * 64 + bh) * 4096;
    #pragma unroll
    for (int i = 0; i < 4; i++)
        *(float4*)(outp + (d0 + i) * 64 + e0) = make_float4(acc[i][0], acc[i][1], acc[i][2], acc[i][3]);
}

__global__ __launch_bounds__(256) void kv_reduce_k(const float* __restrict__ kvp,
                                                   float* __restrict__ kv)
{
    int i = blockIdx.x * 256 + threadIdx.x;
    float s = 0.f;
    #pragma unroll
    for (int spi = 0; spi < 8; spi++) s += kvp[(size_t)spi * 262144 + i];
    kv[i] = s;
}

// ---------------- attn = q @ kv per (b,h), fp16 q in, fp16 out ----------------
__global__ __launch_bounds__(256) void attn_k(const __half* __restrict__ Q,
                                              const float* __restrict__ KV,
                                              __half* __restrict__ Oh)
{
    int bh = blockIdx.x, st = blockIdx.y;
    int b = bh >> 4, h = bh & 15;
    int tid = threadIdx.x;
    __shared__ float kvs[64][64], qs[64][68];
    const float* kvsrc = KV + (size_t)bh * 4096;
    #pragma unroll
    for (int i = 0; i < 4; i++) {
        int f = tid + i * 256;
        int r = f >> 4, c = (f & 15) * 4;
        *(float4*)&kvs[r][c] = *(const float4*)(kvsrc + r * 64 + c);
    }
    size_t qbase = ((size_t)b * 4096 + st * 64) * DM + h * 64;
    #pragma unroll
    for (int i = 0; i < 2; i++) {
        int f = tid + i * 256;           // 0..511
        int r = f >> 3, c = (f & 7) * 8;
        uint4 uq = *(const uint4*)(Q + qbase + (size_t)r * DM + c);
        __half2* hq = (__half2*)&uq;
        #pragma unroll
        for (int t = 0; t < 4; t++) {
            float2 fq = __half22float2(hq[t]);
            qs[r][c + 2*t] = fq.x; qs[r][c + 2*t + 1] = fq.y;
        }
    }
    __syncthreads();
    int r = tid >> 2, e0 = (tid & 3) * 16;
    float acc[16] = {};
    #pragma unroll 8
    for (int d = 0; d < 64; d++) {
        float qd = qs[r][d];
        #pragma unroll
        for (int j = 0; j < 16; j++) acc[j] += qd * kvs[d][e0 + j];
    }
    size_t obase = qbase + (size_t)r * DM + e0;
    #pragma unroll
    for (int j = 0; j < 16; j += 2)
        *(uint32_t*)(Oh + obase + j) = packh(acc[j], acc[j + 1]);
}

// ---------------- launch ----------------
extern "C" void kernel_launch(void* const* d_in, const int* in_sizes, int n_in,
                              void* d_out, int out_size)
{
    const float* x   = (const float*)d_in[0];
    const float* wq  = (const float*)d_in[1];
    const float* bq  = (const float*)d_in[2];
    const float* wk  = (const float*)d_in[3];
    const float* bk  = (const float*)d_in[4];
    const float* wv  = (const float*)d_in[5];
    const float* bv  = (const float*)d_in[6];
    const float* wo  = (const float*)d_in[7];
    const float* bo  = (const float*)d_in[8];
    const float* w1  = (const float*)d_in[9];
    const float* b1  = (const float*)d_in[10];
    const float* w2  = (const float*)d_in[11];
    const float* b2  = (const float*)d_in[12];
    const float* g1  = (const float*)d_in[13];
    const float* be1 = (const float*)d_in[14];
    const float* g2  = (const float*)d_in[15];
    const float* be2 = (const float*)d_in[16];
    float* out = (float*)d_out;

    void* sp = nullptr;
    cudaGetSymbolAddress(&sp, g_scratch);
    unsigned char* S = (unsigned char*)sp;
    __half* Qh   = (__half*)(S + Q_OFF);
    __half* Kh   = (__half*)(S + K_OFF);
    __half* Vh   = (__half*)(S + V_OFF);
    float* X1    = (float*)(S + X1_OFF);
    __half* HH   = (__half*)(S + HH_OFF);
    __half* AH   = (__half*)(S + AH_OFF);
    __half* GH   = (__half*)(S + GH_OFF);
    float* KVb   = (float*)(S + KV_OFF);
    float* KVP   = (float*)(S + KVP_OFF);
    __half* WQKV = (__half*)(S + WQKV_OFF);
    __half* WO2  = (__half*)(S + WO2_OFF);
    __half* W1_  = (__half*)(S + W1_OFF);
    __half* W2_  = (__half*)(S + W2_OFF);

    static bool attr_done = false;
    if (!attr_done) {
        cudaFuncSetAttribute(gemm_mma<4,128>, cudaFuncAttributeMaxDynamicSharedMemorySize, SMEM_G128);
        cudaFuncSetAttribute(gemm_mma<3,128>, cudaFuncAttributeMaxDynamicSharedMemorySize, SMEM_G128);
        cudaFuncSetAttribute(gemm_mma<2,64>,  cudaFuncAttributeMaxDynamicSharedMemorySize, SMEM_G64);
        attr_done = true;
    }

    dim3 wb(32, 8);
    wsplit_k<<<dim3(32, 32), wb>>>(wq, WQKV,               DM, DM);
    wsplit_k<<<dim3(32, 32), wb>>>(wk, WQKV + 1024 * 1024, DM, DM);
    wsplit_k<<<dim3(32, 32), wb>>>(wv, WQKV + 2048 * 1024, DM, DM);
    wsplit_k<<<dim3(32, 32), wb>>>(wo, WO2, DM, DM);
    wsplit_pack_k<<<dim3(256, 32), wb>>>(w1, W1_, DM, 2 * DFF_);
    wsplit_k<<<dim3(32, 128), wb>>>(w2, W2_, DFF_, DM);

    dim3 gQKV(12, 128), gN1024(4, 256), gFF1(32, 128);

    // LN1
    ln_k<<<M_TOT, 256>>>(x, g1, be1, HH);
    // fused q/k/v projection (elu+1 on q,k) -> fp16
    gemm_mma<4,128><<<gQKV, 256, SMEM_G128>>>(HH, WQKV, bq, bk, bv, nullptr,
                                              nullptr, Qh, Kh, Vh, nullptr, DM, 1024);
    // linear attention
    kv_partial_k<<<dim3(64, 8), 256>>>(Kh, Vh, KVP);
    kv_reduce_k<<<1024, 256>>>(KVP, KVb);
    attn_k<<<dim3(64, 64), 256>>>(Qh, KVb, AH);
    // out proj + residual(x) — TM=64 tile: 1024 CTAs, less wave quantization
    gemm_mma<2,64><<<gN1024, 256, SMEM_G64>>>(AH, WO2, bo, nullptr, nullptr, x,
                                              X1, nullptr, nullptr, nullptr, nullptr, DM, DM);
    // LN2
    ln_k<<<M_TOT, 256>>>(X1, g2, be2, HH);
    // FF1 + fused GEGLU -> fp16
    gemm_mma<3,128><<<gFF1, 256, SMEM_G128>>>(HH, W1_, b1, nullptr, nullptr, nullptr,
                                              nullptr, nullptr, nullptr, nullptr, GH, DM, DFF_);
    // FF2 + residual(X1) — TM=64 tile
    gemm_mma<2,64><<<gN1024, 256, SMEM_G64>>>(GH, W2_, b2, nullptr, nullptr, X1,
                                              out, nullptr, nullptr, nullptr, nullptr, DFF_, DM);
}

// round 16
// speedup vs baseline: 1.1034x; 1.0167x over previous
#include <cuda_runtime.h>
#include <cuda_fp16.h>
#include <math.h>
#include <stdint.h>

#define M_TOT   16384
#define DM      1024
#define DFF_    4096
#define MB(x)   ((size_t)(x) * 1048576ull)

// ---------------- scratch (byte offsets) ----------------
// Q/K/V fp16 (32MB), X1 fp32 (64MB), HH/AH fp16 (32MB), GH fp16 (128MB)
#define Q_OFF     MB(0)
#define K_OFF     MB(32)
#define V_OFF     MB(64)
#define X1_OFF    MB(96)
#define HH_OFF    MB(160)
#define AH_OFF    MB(192)
#define GH_OFF    MB(224)     // ..MB(352)
#define KV_OFF    MB(352)
#define KVP_OFF   MB(353)
#define WQKV_OFF  MB(361)
#define WO2_OFF   MB(367)
#define W1_OFF    MB(369)
#define W2_OFF    MB(385)
#define SCR_TOT   MB(393)

__device__ __align__(1024) unsigned char g_scratch[SCR_TOT];

// ---------------- PTX helpers (non-'a' ISA only) ----------------
__device__ __forceinline__ uint32_t smem_u32(const void* p) {
    uint32_t a;
    asm("{ .reg .u64 t; cvta.to.shared.u64 t, %1; cvt.u32.u64 %0, t; }" : "=r"(a) : "l"(p));
    return a;
}
__device__ __forceinline__ void cp16(uint32_t dst, const void* src) {
    asm volatile("cp.async.cg.shared.global [%0], [%1], 16;" :: "r"(dst), "l"(src) : "memory");
}
#define CP_COMMIT() asm volatile("cp.async.commit_group;" ::: "memory")
#define CP_WAIT(n)  asm volatile("cp.async.wait_group %0;" :: "n"(n) : "memory")

__device__ __forceinline__ void ldm4(uint32_t* r, uint32_t addr) {
    asm volatile("ldmatrix.sync.aligned.m8n8.x4.shared.b16 {%0,%1,%2,%3}, [%4];"
        : "=r"(r[0]), "=r"(r[1]), "=r"(r[2]), "=r"(r[3]) : "r"(addr));
}
__device__ __forceinline__ void mma16816(float* c, const uint32_t* a, const uint32_t* b) {
    asm volatile("mma.sync.aligned.m16n8k16.row.col.f32.f16.f16.f32 "
        "{%0,%1,%2,%3}, {%4,%5,%6,%7}, {%8,%9}, {%0,%1,%2,%3};"
        : "+f"(c[0]), "+f"(c[1]), "+f"(c[2]), "+f"(c[3])
        : "r"(a[0]), "r"(a[1]), "r"(a[2]), "r"(a[3]), "r"(b[0]), "r"(b[1]));
}
__device__ __forceinline__ uint32_t packh(float a, float b) {
    __half2 t = __floats2half2_rn(a, b);
    return *(uint32_t*)&t;
}

// smem tile geometry: K-chunk 64 fp16 = 128B data + 16B pad -> 144B rows
#define ROWB    144u
#define APIECE  18432u        // 128 rows * 144B
#define BPIECE  36864u        // 256 rows * 144B
#define STAGEB  55296u        // A + B
#define NSTAGE  3
#define SMEM_GEMM (NSTAGE * 55296)

// -------- weight transpose: W[K x N] fp32 -> fp16 [N x K] --------
__global__ void wsplit_k(const float* __restrict__ W,
                         __half* __restrict__ out, int K, int N)
{
    __shared__ float t[32][33];
    int tx = threadIdx.x, ty = threadIdx.y;
    int n0 = blockIdx.x * 32, k0 = blockIdx.y * 32;
    #pragma unroll
    for (int i = 0; i < 4; i++)
        t[ty + i * 8][tx] = W[(size_t)(k0 + ty + i * 8) * N + n0 + tx];
    __syncthreads();
    #pragma unroll
    for (int i = 0; i < 4; i++)
        out[(size_t)(n0 + ty + i * 8) * K + k0 + tx] = __float2half(t[tx][ty + i * 8]);
}

// packed variant for W1: interleave 8 gate cols / 8 lin cols per 16 dst rows
__global__ void wsplit_pack_k(const float* __restrict__ W,
                              __half* __restrict__ out, int K, int N)
{
    __shared__ float t[32][33];
    int tx = threadIdx.x, ty = threadIdx.y;
    int n0 = blockIdx.x * 32, k0 = blockIdx.y * 32;
    #pragma unroll
    for (int i = 0; i < 4; i++)
        t[ty + i * 8][tx] = W[(size_t)(k0 + ty + i * 8) * N + n0 + tx];
    __syncthreads();
    #pragma unroll
    for (int i = 0; i < 4; i++) {
        int n = n0 + ty + i * 8;
        int dr = (n < 4096) ? ((n >> 3) * 16 + (n & 7))
                            : (((n - 4096) >> 3) * 16 + 8 + (n & 7));
        out[(size_t)dr * K + k0 + tx] = __float2half(t[tx][ty + i * 8]);
    }
}

// ---------------- layernorm -> fp16 ----------------
__global__ __launch_bounds__(256) void ln_k(const float* __restrict__ x,
                                            const float* __restrict__ gamma,
                                            const float* __restrict__ beta,
                                            __half* __restrict__ hh)
{
    int row = blockIdx.x, tid = threadIdx.x;
    float4 v = ((const float4*)(x + (size_t)row * DM))[tid];
    float s  = v.x + v.y + v.z + v.w;
    float ss = v.x*v.x + v.y*v.y + v.z*v.z + v.w*v.w;
    #pragma unroll
    for (int o = 16; o; o >>= 1) {
        s  += __shfl_xor_sync(0xffffffffu, s,  o);
        ss += __shfl_xor_sync(0xffffffffu, ss, o);
    }
    __shared__ float shs[8], shss[8], smu, srs;
    int w = tid >> 5, lane = tid & 31;
    if (lane == 0) { shs[w] = s; shss[w] = ss; }
    __syncthreads();
    if (tid == 0) {
        float ts = 0.f, tss = 0.f;
        #pragma unroll
        for (int i = 0; i < 8; i++) { ts += shs[i]; tss += shss[i]; }
        float mu  = ts * (1.0f / DM);
        float var = tss * (1.0f / DM) - mu * mu;
        smu = mu; srs = rsqrtf(var + 1e-5f);
    }
    __syncthreads();
    float mu = smu, rs = srs;
    float4 g = ((const float4*)gamma)[tid];
    float4 b = ((const float4*)beta)[tid];
    __align__(8) __half hb[4];
    hb[0] = __float2half((v.x-mu)*rs*g.x + b.x);
    hb[1] = __float2half((v.y-mu)*rs*g.y + b.y);
    hb[2] = __float2half((v.z-mu)*rs*g.z + b.z);
    hb[3] = __float2half((v.w-mu)*rs*g.w + b.w);
    ((uint2*)(hh + (size_t)row * DM))[tid] = *(uint2*)hb;
}

// ---------------- mma.sync GEMM: tile 128x256x64, 256 thr, warp tile 64x64,
// 3-stage cp.async. C = A[MxK] @ (B[NxK])^T, f32 accum.
// EPI: 2 = +bias +residual (fp32 out), 3 = geglu -> fp16, 4 = fused QKV -> fp16
template<int EPI>
__global__ __launch_bounds__(256) void gemm_mma(
    const __half* __restrict__ A, const __half* __restrict__ B,
    const float* __restrict__ b0, const float* __restrict__ b1,
    const float* __restrict__ b2, const float* __restrict__ Rres,
    float* __restrict__ C0,
    __half* __restrict__ H0, __half* __restrict__ H1, __half* __restrict__ H2,
    __half* __restrict__ Gout,
    int Kdim, int Nout)
{
    extern __shared__ unsigned char dsm[];
    const int tid = threadIdx.x, wid = tid >> 5, lane = tid & 31;
    const int m0 = blockIdx.y * 128, n0 = blockIdx.x * 256;
    const int warp_m = (wid >> 2) * 64, warp_n = (wid & 3) * 64;
    const uint32_t dbase = smem_u32(dsm);

    auto fill = [&](int stage, int chunk) {
        uint32_t sb = dbase + (uint32_t)stage * STAGEB;
        int k0 = chunk << 6;
        #pragma unroll
        for (int it = 0; it < 12; it++) {
            int idx = tid + it * 256;          // 0..3071
            if (idx < 1024) {
                int row = idx >> 3, c = idx & 7;
                cp16(sb + (uint32_t)row * ROWB + (uint32_t)c * 16u,
                     A + (size_t)(m0 + row) * Kdim + k0 + c * 8);
            } else {
                int l = idx - 1024;            // 0..2047
                int row = l >> 3, c = l & 7;
                cp16(sb + APIECE + (uint32_t)row * ROWB + (uint32_t)c * 16u,
                     B + (size_t)(n0 + row) * Kdim + k0 + c * 8);
            }
        }
    };

    float acc[4][8][4];
    #pragma unroll
    for (int i = 0; i < 4; i++)
        #pragma unroll
        for (int j = 0; j < 8; j++)
            #pragma unroll
            for (int t = 0; t < 4; t++) acc[i][j][t] = 0.f;

    const int nk = Kdim >> 6;
    fill(0, 0); CP_COMMIT();
    if (nk > 1) { fill(1, 1); CP_COMMIT(); }

    int stage = 0;
    for (int c = 0; c < nk; c++) {
        if (c + 1 < nk) CP_WAIT(1);
        else            CP_WAIT(0);
        __syncthreads();
        if (c + 2 < nk) {
            int fs = stage + 2; if (fs >= NSTAGE) fs -= NSTAGE;
            fill(fs, c + 2); CP_COMMIT();
        }

        uint32_t sb = dbase + (uint32_t)stage * STAGEB;
        uint32_t aoff = sb, boff = sb + APIECE;

        #pragma unroll
        for (int ks = 0; ks < 4; ks++) {
            uint32_t af[4][4];
            {
                int arow = warp_m + (lane & 15);
                uint32_t acol = (uint32_t)(ks * 2 + (lane >> 4)) * 16u;
                #pragma unroll
                for (int mt = 0; mt < 4; mt++)
                    ldm4(af[mt], aoff + (uint32_t)(arow + mt * 16) * ROWB + acol);
            }
            int brow = warp_n + (lane & 7) + ((lane >> 4) * 8);
            uint32_t bcol = (uint32_t)(ks * 2 + ((lane >> 3) & 1)) * 16u;
            #pragma unroll
            for (int np = 0; np < 4; np++) {
                uint32_t r[4];
                ldm4(r, boff + (uint32_t)(brow + np * 16) * ROWB + bcol);
                uint32_t bb0[2] = { r[0], r[1] }, bb1[2] = { r[2], r[3] };
                #pragma unroll
                for (int mt = 0; mt < 4; mt++) {
                    mma16816(acc[mt][np * 2 + 0], af[mt], bb0);
                    mma16816(acc[mt][np * 2 + 1], af[mt], bb1);
                }
            }
        }
        if (++stage >= NSTAGE) stage = 0;
    }

    // ---------------- epilogue ----------------
    int gid = lane >> 2, tig = lane & 3;
    if (EPI == 3) {
        const float is2 = 0.70710678118654752f;
        #pragma unroll
        for (int mt = 0; mt < 4; mt++) {
            int r0 = m0 + warp_m + mt * 16 + gid;
            #pragma unroll
            for (int j = 0; j < 4; j++) {
                int rc = ((n0 + warp_n) >> 1) + j * 8 + tig * 2;
                float2 bg = *(const float2*)(b0 + rc);
                float2 bl = *(const float2*)(b0 + 4096 + rc);
                float gv[4] = { acc[mt][2*j][0] + bg.x, acc[mt][2*j][1] + bg.y,
                                acc[mt][2*j][2] + bg.x, acc[mt][2*j][3] + bg.y };
                float lv[4] = { acc[mt][2*j+1][0] + bl.x, acc[mt][2*j+1][1] + bl.y,
                                acc[mt][2*j+1][2] + bl.x, acc[mt][2*j+1][3] + bl.y };
                float o[4];
                #pragma unroll
                for (int t = 0; t < 4; t++)
                    o[t] = 0.5f * gv[t] * (1.f + erff(gv[t] * is2)) * lv[t];
                size_t o0 = (size_t)r0 * 4096 + rc;
                size_t o1 = (size_t)(r0 + 8) * 4096 + rc;
                *(uint32_t*)(Gout + o0) = packh(o[0], o[1]);
                *(uint32_t*)(Gout + o1) = packh(o[2], o[3]);
            }
        }
    } else if (EPI == 4) {
        #pragma unroll
        for (int mt = 0; mt < 4; mt++) {
            int r0 = m0 + warp_m + mt * 16 + gid;
            #pragma unroll
            for (int nt = 0; nt < 8; nt++) {
                int col = n0 + warp_n + nt * 8 + tig * 2;   // global in [0,3072)
                const float* bp; __half* Hp; int cl; bool elu;
                if (col < 1024)      { bp = b0 + col;        Hp = H0; cl = col;        elu = true; }
                else if (col < 2048) { bp = b1 + col - 1024; Hp = H1; cl = col - 1024; elu = true; }
                else                 { bp = b2 + col - 2048; Hp = H2; cl = col - 2048; elu = false; }
                float2 bb = *(const float2*)bp;
                float v0 = acc[mt][nt][0] + bb.x, v1 = acc[mt][nt][1] + bb.y;
                float v2 = acc[mt][nt][2] + bb.x, v3 = acc[mt][nt][3] + bb.y;
                if (elu) {
                    v0 = (v0 > 0.f) ? (v0 + 1.f) : expf(v0);
                    v1 = (v1 > 0.f) ? (v1 + 1.f) : expf(v1);
                    v2 = (v2 > 0.f) ? (v2 + 1.f) : expf(v2);
                    v3 = (v3 > 0.f) ? (v3 + 1.f) : expf(v3);
                }
                *(uint32_t*)(Hp + (size_t)r0 * 1024 + cl)       = packh(v0, v1);
                *(uint32_t*)(Hp + (size_t)(r0 + 8) * 1024 + cl) = packh(v2, v3);
            }
        }
    } else {  // EPI == 2
        #pragma unroll
        for (int mt = 0; mt < 4; mt++) {
            int r0 = m0 + warp_m + mt * 16 + gid;
            #pragma unroll
            for (int nt = 0; nt < 8; nt++) {
                int col = n0 + warp_n + nt * 8 + tig * 2;
                float2 bb = *(const float2*)(b0 + col);
                float v0 = acc[mt][nt][0] + bb.x, v1 = acc[mt][nt][1] + bb.y;
                float v2 = acc[mt][nt][2] + bb.x, v3 = acc[mt][nt][3] + bb.y;
                size_t o0 = (size_t)r0 * Nout + col;
                size_t o1 = (size_t)(r0 + 8) * Nout + col;
                float2 ra = *(const float2*)(Rres + o0);
                float2 rb = *(const float2*)(Rres + o1);
                v0 += ra.x; v1 += ra.y; v2 += rb.x; v3 += rb.y;
                *(float2*)(C0 + o0) = make_float2(v0, v1);
                *(float2*)(C0 + o1) = make_float2(v2, v3);
            }
        }
    }
}

// ---------------- kv = K^T V per (b,h), split over S (fp16 in) ----------------
__global__ __launch_bounds__(256) void kv_partial_k(const __half* __restrict__ Kp,
                                                    const __half* __restrict__ Vp,
                                                    float* __restrict__ kvp)
{
    int bh = blockIdx.x, spi = blockIdx.y;
    int b = bh >> 4, h = bh & 15;
    int tid = threadIdx.x;
    __shared__ float ks[32][64], vs[32][64];
    float acc[4][4] = {};
    int d0 = (tid >> 4) * 4, e0 = (tid & 15) * 4;
    size_t base = ((size_t)b * 4096) * DM + h * 64;
    for (int s0 = spi * 512; s0 < spi * 512 + 512; s0 += 32) {
        {
            int r = tid >> 3, c = (tid & 7) * 8;
            size_t off = base + (size_t)(s0 + r) * DM + c;
            uint4 uk = *(const uint4*)(Kp + off);
            uint4 uv = *(const uint4*)(Vp + off);
            __half2* hk = (__half2*)&uk;
            __half2* hv = (__half2*)&uv;
            #pragma unroll
            for (int t = 0; t < 4; t++) {
                float2 fk = __half22float2(hk[t]);
                float2 fv = __half22float2(hv[t]);
                ks[r][c + 2*t] = fk.x; ks[r][c + 2*t + 1] = fk.y;
                vs[r][c + 2*t] = fv.x; vs[r][c + 2*t + 1] = fv.y;
            }
        }
        __syncthreads();
        #pragma unroll
        for (int ssm = 0; ssm < 32; ssm++) {
            float kd[4] = { ks[ssm][d0], ks[ssm][d0+1], ks[ssm][d0+2], ks[ssm][d0+3] };
            float ve[4] = { vs[ssm][e0], vs[ssm][e0+1], vs[ssm][e0+2], vs[ssm][e0+3] };
            #pragma unroll
            for (int i = 0; i < 4; i++)
                #pragma unroll
                for (int j = 0; j < 4; j++) acc[i][j] += kd[i] * ve[j];
        }
        __syncthreads();
    }
    float* outp = kvp + ((size_t)spi * 64 + bh) * 4096;
    #pragma unroll
    for (int i = 0; i < 4; i++)
        *(float4*)(outp + (d0 + i) * 64 + e0) = make_float4(acc[i][0], acc[i][1], acc[i][2], acc[i][3]);
}

__global__ __launch_bounds__(256) void kv_reduce_k(const float* __restrict__ kvp,
                                                   float* __restrict__ kv)
{
    int i = blockIdx.x * 256 + threadIdx.x;
    float s = 0.f;
    #pragma unroll
    for (int spi = 0; spi < 8; spi++) s += kvp[(size_t)spi * 262144 + i];
    kv[i] = s;
}

// ---------------- attn = q @ kv per (b,h), fp16 q in, fp16 out ----------------
__global__ __launch_bounds__(256) void attn_k(const __half* __restrict__ Q,
                                              const float* __restrict__ KV,
                                              __half* __restrict__ Oh)
{
    int bh = blockIdx.x, st = blockIdx.y;
    int b = bh >> 4, h = bh & 15;
    int tid = threadIdx.x;
    __shared__ float kvs[64][64], qs[64][68];
    const float* kvsrc = KV + (size_t)bh * 4096;
    #pragma unroll
    for (int i = 0; i < 4; i++) {
        int f = tid + i * 256;
        int r = f >> 4, c = (f & 15) * 4;
        *(float4*)&kvs[r][c] = *(const float4*)(kvsrc + r * 64 + c);
    }
    size_t qbase = ((size_t)b * 4096 + st * 64) * DM + h * 64;
    #pragma unroll
    for (int i = 0; i < 2; i++) {
        int f = tid + i * 256;           // 0..511
        int r = f >> 3, c = (f & 7) * 8;
        uint4 uq = *(const uint4*)(Q + qbase + (size_t)r * DM + c);
        __half2* hq = (__half2*)&uq;
        #pragma unroll
        for (int t = 0; t < 4; t++) {
            float2 fq = __half22float2(hq[t]);
            qs[r][c + 2*t] = fq.x; qs[r][c + 2*t + 1] = fq.y;
        }
    }
    __syncthreads();
    int r = tid >> 2, e0 = (tid & 3) * 16;
    float acc[16] = {};
    #pragma unroll 8
    for (int d = 0; d < 64; d++) {
        float qd = qs[r][d];
        #pragma unroll
        for (int j = 0; j < 16; j++) acc[j] += qd * kvs[d][e0 + j];
    }
    size_t obase = qbase + (size_t)r * DM + e0;
    #pragma unroll
    for (int j = 0; j < 16; j += 2)
        *(uint32_t*)(Oh + obase + j) = packh(acc[j], acc[j + 1]);
}

// ---------------- launch ----------------
extern "C" void kernel_launch(void* const* d_in, const int* in_sizes, int n_in,
                              void* d_out, int out_size)
{
    const float* x   = (const float*)d_in[0];
    const float* wq  = (const float*)d_in[1];
    const float* bq  = (const float*)d_in[2];
    const float* wk  = (const float*)d_in[3];
    const float* bk  = (const float*)d_in[4];
    const float* wv  = (const float*)d_in[5];
    const float* bv  = (const float*)d_in[6];
    const float* wo  = (const float*)d_in[7];
    const float* bo  = (const float*)d_in[8];
    const float* w1  = (const float*)d_in[9];
    const float* b1  = (const float*)d_in[10];
    const float* w2  = (const float*)d_in[11];
    const float* b2  = (const float*)d_in[12];
    const float* g1  = (const float*)d_in[13];
    const float* be1 = (const float*)d_in[14];
    const float* g2  = (const float*)d_in[15];
    const float* be2 = (const float*)d_in[16];
    float* out = (float*)d_out;

    void* sp = nullptr;
    cudaGetSymbolAddress(&sp, g_scratch);
    unsigned char* S = (unsigned char*)sp;
    __half* Qh   = (__half*)(S + Q_OFF);
    __half* Kh   = (__half*)(S + K_OFF);
    __half* Vh   = (__half*)(S + V_OFF);
    float* X1    = (float*)(S + X1_OFF);
    __half* HH   = (__half*)(S + HH_OFF);
    __half* AH   = (__half*)(S + AH_OFF);
    __half* GH   = (__half*)(S + GH_OFF);
    float* KVb   = (float*)(S + KV_OFF);
    float* KVP   = (float*)(S + KVP_OFF);
    __half* WQKV = (__half*)(S + WQKV_OFF);
    __half* WO2  = (__half*)(S + WO2_OFF);
    __half* W1_  = (__half*)(S + W1_OFF);
    __half* W2_  = (__half*)(S + W2_OFF);

    static bool attr_done = false;
    if (!attr_done) {
        cudaFuncSetAttribute(gemm_mma<2>, cudaFuncAttributeMaxDynamicSharedMemorySize, SMEM_GEMM);
        cudaFuncSetAttribute(gemm_mma<3>, cudaFuncAttributeMaxDynamicSharedMemorySize, SMEM_GEMM);
        cudaFuncSetAttribute(gemm_mma<4>, cudaFuncAttributeMaxDynamicSharedMemorySize, SMEM_GEMM);
        attr_done = true;
    }

    dim3 wb(32, 8);
    wsplit_k<<<dim3(32, 32), wb>>>(wq, WQKV,               DM, DM);
    wsplit_k<<<dim3(32, 32), wb>>>(wk, WQKV + 1024 * 1024, DM, DM);
    wsplit_k<<<dim3(32, 32), wb>>>(wv, WQKV + 2048 * 1024, DM, DM);
    wsplit_k<<<dim3(32, 32), wb>>>(wo, WO2, DM, DM);
    wsplit_pack_k<<<dim3(256, 32), wb>>>(w1, W1_, DM, 2 * DFF_);
    wsplit_k<<<dim3(32, 128), wb>>>(w2, W2_, DFF_, DM);

    dim3 gQKV(12, 128), gN1024(4, 128), gFF1(32, 128);

    // LN1
    ln_k<<<M_TOT, 256>>>(x, g1, be1, HH);
    // fused q/k/v projection (elu+1 on q,k) -> fp16
    gemm_mma<4><<<gQKV, 256, SMEM_GEMM>>>(HH, WQKV, bq, bk, bv, nullptr,
                                          nullptr, Qh, Kh, Vh, nullptr, DM, 1024);
    // linear attention
    kv_partial_k<<<dim3(64, 8), 256>>>(Kh, Vh, KVP);
    kv_reduce_k<<<1024, 256>>>(KVP, KVb);
    attn_k<<<dim3(64, 64), 256>>>(Qh, KVb, AH);
    // out proj + residual(x)
    gemm_mma<2><<<gN1024, 256, SMEM_GEMM>>>(AH, WO2, bo, nullptr, nullptr, x,
                                            X1, nullptr, nullptr, nullptr, nullptr, DM, DM);
    // LN2
    ln_k<<<M_TOT, 256>>>(X1, g2, be2, HH);
    // FF1 + fused GEGLU -> fp16
    gemm_mma<3><<<gFF1, 256, SMEM_GEMM>>>(HH, W1_, b1, nullptr, nullptr, nullptr,
                                          nullptr, nullptr, nullptr, nullptr, GH, DM, DFF_);
    // FF2 + residual(X1)
    gemm_mma<2><<<gN1024, 256, SMEM_GEMM>>>(GH, W2_, b2, nullptr, nullptr, X1,
                                            out, nullptr, nullptr, nullptr, nullptr, DFF_, DM);
}

// round 17
// speedup vs baseline: 1.1207x; 1.0157x over previous
#include <cuda_runtime.h>
#include <cuda_fp16.h>
#include <math.h>
#include <stdint.h>

#define M_TOT   16384
#define DM      1024
#define DFF_    4096
#define MB(x)   ((size_t)(x) * 1048576ull)

// ---------------- scratch (byte offsets) ----------------
#define Q_OFF     MB(0)
#define K_OFF     MB(64)
#define V_OFF     MB(128)
#define X1_OFF    MB(192)
#define HH_OFF    MB(256)
#define AH_OFF    MB(288)
#define GH_OFF    MB(320)     // ..MB(448)
#define KV_OFF    MB(448)
#define KVP_OFF   MB(449)
#define WQKV_OFF  MB(457)
#define WO2_OFF   MB(463)
#define W1_OFF    MB(465)
#define W2_OFF    MB(481)
#define SCR_TOT   MB(489)

__device__ __align__(1024) unsigned char g_scratch[SCR_TOT];

// ---------------- PTX helpers (non-'a' ISA only) ----------------
__device__ __forceinline__ uint32_t smem_u32(const void* p) {
    uint32_t a;
    asm("{ .reg .u64 t; cvta.to.shared.u64 t, %1; cvt.u32.u64 %0, t; }" : "=r"(a) : "l"(p));
    return a;
}
__device__ __forceinline__ void cp16(uint32_t dst, const void* src) {
    asm volatile("cp.async.cg.shared.global [%0], [%1], 16;" :: "r"(dst), "l"(src) : "memory");
}
#define CP_COMMIT() asm volatile("cp.async.commit_group;" ::: "memory")
#define CP_WAIT(n)  asm volatile("cp.async.wait_group %0;" :: "n"(n) : "memory")

__device__ __forceinline__ void ldm4(uint32_t* r, uint32_t addr) {
    asm volatile("ldmatrix.sync.aligned.m8n8.x4.shared.b16 {%0,%1,%2,%3}, [%4];"
        : "=r"(r[0]), "=r"(r[1]), "=r"(r[2]), "=r"(r[3]) : "r"(addr));
}
__device__ __forceinline__ void mma16816(float* c, const uint32_t* a, const uint32_t* b) {
    asm volatile("mma.sync.aligned.m16n8k16.row.col.f32.f16.f16.f32 "
        "{%0,%1,%2,%3}, {%4,%5,%6,%7}, {%8,%9}, {%0,%1,%2,%3};"
        : "+f"(c[0]), "+f"(c[1]), "+f"(c[2]), "+f"(c[3])
        : "r"(a[0]), "r"(a[1]), "r"(a[2]), "r"(a[3]), "r"(b[0]), "r"(b[1]));
}
__device__ __forceinline__ uint32_t packh(float a, float b) {
    __half2 t = __floats2half2_rn(a, b);
    return *(uint32_t*)&t;
}

// smem tile geometry: K-chunk 128 fp16 = 256B data + 16B pad -> 272B rows
// (row stride 68 words == 4 mod 32 -> 8-row ldmatrix phases conflict-free)
#define ROWB    272u
#define APIECE  34816u        // 128 rows * 272B
#define BPIECE  69632u        // 256 rows * 272B
#define STAGEB  104448u       // A + B
#define SMEM_GEMM (2 * 104448)

// -------- weight transpose: W[K x N] fp32 -> fp16 [N x K] --------
__global__ void wsplit_k(const float* __restrict__ W,
                         __half* __restrict__ out, int K, int N)
{
    __shared__ float t[32][33];
    int tx = threadIdx.x, ty = threadIdx.y;
    int n0 = blockIdx.x * 32, k0 = blockIdx.y * 32;
    #pragma unroll
    for (int i = 0; i < 4; i++)
        t[ty + i * 8][tx] = W[(size_t)(k0 + ty + i * 8) * N + n0 + tx];
    __syncthreads();
    #pragma unroll
    for (int i = 0; i < 4; i++)
        out[(size_t)(n0 + ty + i * 8) * K + k0 + tx] = __float2half(t[tx][ty + i * 8]);
}

// packed variant for W1: interleave 8 gate cols / 8 lin cols per 16 dst rows
__global__ void wsplit_pack_k(const float* __restrict__ W,
                              __half* __restrict__ out, int K, int N)
{
    __shared__ float t[32][33];
    int tx = threadIdx.x, ty = threadIdx.y;
    int n0 = blockIdx.x * 32, k0 = blockIdx.y * 32;
    #pragma unroll
    for (int i = 0; i < 4; i++)
        t[ty + i * 8][tx] = W[(size_t)(k0 + ty + i * 8) * N + n0 + tx];
    __syncthreads();
    #pragma unroll
    for (int i = 0; i < 4; i++) {
        int n = n0 + ty + i * 8;
        int dr = (n < 4096) ? ((n >> 3) * 16 + (n & 7))
                            : (((n - 4096) >> 3) * 16 + 8 + (n & 7));
        out[(size_t)dr * K + k0 + tx] = __float2half(t[tx][ty + i * 8]);
    }
}

// ---------------- layernorm -> fp16 ----------------
__global__ __launch_bounds__(256) void ln_k(const float* __restrict__ x,
                                            const float* __restrict__ gamma,
                                            const float* __restrict__ beta,
                                            __half* __restrict__ hh)
{
    int row = blockIdx.x, tid = threadIdx.x;
    float4 v = ((const float4*)(x + (size_t)row * DM))[tid];
    float s  = v.x + v.y + v.z + v.w;
    float ss = v.x*v.x + v.y*v.y + v.z*v.z + v.w*v.w;
    #pragma unroll
    for (int o = 16; o; o >>= 1) {
        s  += __shfl_xor_sync(0xffffffffu, s,  o);
        ss += __shfl_xor_sync(0xffffffffu, ss, o);
    }
    __shared__ float shs[8], shss[8], smu, srs;
    int w = tid >> 5, lane = tid & 31;
    if (lane == 0) { shs[w] = s; shss[w] = ss; }
    __syncthreads();
    if (tid == 0) {
        float ts = 0.f, tss = 0.f;
        #pragma unroll
        for (int i = 0; i < 8; i++) { ts += shs[i]; tss += shss[i]; }
        float mu  = ts * (1.0f / DM);
        float var = tss * (1.0f / DM) - mu * mu;
        smu = mu; srs = rsqrtf(var + 1e-5f);
    }
    __syncthreads();
    float mu = smu, rs = srs;
    float4 g = ((const float4*)gamma)[tid];
    float4 b = ((const float4*)beta)[tid];
    __align__(8) __half hb[4];
    hb[0] = __float2half((v.x-mu)*rs*g.x + b.x);
    hb[1] = __float2half((v.y-mu)*rs*g.y + b.y);
    hb[2] = __float2half((v.z-mu)*rs*g.z + b.z);
    hb[3] = __float2half((v.w-mu)*rs*g.w + b.w);
    ((uint2*)(hh + (size_t)row * DM))[tid] = *(uint2*)hb;
}

// ---------------- mma.sync GEMM: tile 128x256x128, 256 thr, warp tile 64x64,
// double-buffered cp.async. C = A[MxK] @ (B[NxK])^T, f32 accum.
// EPI: 2 = +bias +residual (fp32 out), 3 = geglu -> fp16, 4 = fused QKV route
template<int EPI>
__global__ __launch_bounds__(256) void gemm_mma(
    const __half* __restrict__ A, const __half* __restrict__ B,
    const float* __restrict__ b0, const float* __restrict__ b1,
    const float* __restrict__ b2, const float* __restrict__ Rres,
    float* __restrict__ C0, float* __restrict__ C1, float* __restrict__ C2,
    __half* __restrict__ Gout,
    int Kdim, int Nout)
{
    extern __shared__ unsigned char dsm[];
    const int tid = threadIdx.x, wid = tid >> 5, lane = tid & 31;
    const int m0 = blockIdx.y * 128, n0 = blockIdx.x * 256;
    const int warp_m = (wid >> 2) * 64, warp_n = (wid & 3) * 64;
    const uint32_t dbase = smem_u32(dsm);

    auto fill = [&](int stage, int chunk) {
        uint32_t sb = dbase + (uint32_t)stage * STAGEB;
        int k0 = chunk << 7;
        #pragma unroll
        for (int it = 0; it < 24; it++) {
            int idx = tid + it * 256;          // 0..6143
            if (idx < 2048) {
                int row = idx >> 4, c = idx & 15;
                cp16(sb + (uint32_t)row * ROWB + (uint32_t)c * 16u,
                     A + (size_t)(m0 + row) * Kdim + k0 + c * 8);
            } else {
                int l = idx - 2048;            // 0..4095
                int row = l >> 4, c = l & 15;
                cp16(sb + APIECE + (uint32_t)row * ROWB + (uint32_t)c * 16u,
                     B + (size_t)(n0 + row) * Kdim + k0 + c * 8);
            }
        }
    };

    float acc[4][8][4];
    #pragma unroll
    for (int i = 0; i < 4; i++)
        #pragma unroll
        for (int j = 0; j < 8; j++)
            #pragma unroll
            for (int t = 0; t < 4; t++) acc[i][j][t] = 0.f;

    const int nk = Kdim >> 7;
    fill(0, 0); CP_COMMIT();

    for (int c = 0; c < nk; c++) {
        int cur = c & 1;
        if (c + 1 < nk) { fill(1 - cur, c + 1); CP_COMMIT(); CP_WAIT(1); }
        else CP_WAIT(0);
        __syncthreads();

        uint32_t sb = dbase + (uint32_t)cur * STAGEB;
        uint32_t aoff = sb, boff = sb + APIECE;

        #pragma unroll
        for (int ks = 0; ks < 8; ks++) {
            uint32_t af[4][4];
            {
                int arow = warp_m + (lane & 15);
                uint32_t acol = (uint32_t)(ks * 2 + (lane >> 4)) * 16u;
                #pragma unroll
                for (int mt = 0; mt < 4; mt++)
                    ldm4(af[mt], aoff + (uint32_t)(arow + mt * 16) * ROWB + acol);
            }
            int brow = warp_n + (lane & 7) + ((lane >> 4) * 8);
            uint32_t bcol = (uint32_t)(ks * 2 + ((lane >> 3) & 1)) * 16u;
            #pragma unroll
            for (int np = 0; np < 4; np++) {
                uint32_t r[4];
                ldm4(r, boff + (uint32_t)(brow + np * 16) * ROWB + bcol);
                uint32_t bb0[2] = { r[0], r[1] }, bb1[2] = { r[2], r[3] };
                #pragma unroll
                for (int mt = 0; mt < 4; mt++) {
                    mma16816(acc[mt][np * 2 + 0], af[mt], bb0);
                    mma16816(acc[mt][np * 2 + 1], af[mt], bb1);
                }
            }
        }
        __syncthreads();
    }

    // ---------------- epilogue ----------------
    int gid = lane >> 2, tig = lane & 3;
    if (EPI == 3) {
        const float is2 = 0.70710678118654752f;
        #pragma unroll
        for (int mt = 0; mt < 4; mt++) {
            int r0 = m0 + warp_m + mt * 16 + gid;
            #pragma unroll
            for (int j = 0; j < 4; j++) {
                int rc = ((n0 + warp_n) >> 1) + j * 8 + tig * 2;
                float2 bg = *(const float2*)(b0 + rc);
                float2 bl = *(const float2*)(b0 + 4096 + rc);
                float gv[4] = { acc[mt][2*j][0] + bg.x, acc[mt][2*j][1] + bg.y,
                                acc[mt][2*j][2] + bg.x, acc[mt][2*j][3] + bg.y };
                float lv[4] = { acc[mt][2*j+1][0] + bl.x, acc[mt][2*j+1][1] + bl.y,
                                acc[mt][2*j+1][2] + bl.x, acc[mt][2*j+1][3] + bl.y };
                float o[4];
                #pragma unroll
                for (int t = 0; t < 4; t++)
                    o[t] = 0.5f * gv[t] * (1.f + erff(gv[t] * is2)) * lv[t];
                size_t o0 = (size_t)r0 * 4096 + rc;
                size_t o1 = (size_t)(r0 + 8) * 4096 + rc;
                *(uint32_t*)(Gout + o0) = packh(o[0], o[1]);
                *(uint32_t*)(Gout + o1) = packh(o[2], o[3]);
            }
        }
    } else if (EPI == 4) {
        #pragma unroll
        for (int mt = 0; mt < 4; mt++) {
            int r0 = m0 + warp_m + mt * 16 + gid;
            #pragma unroll
            for (int nt = 0; nt < 8; nt++) {
                int col = n0 + warp_n + nt * 8 + tig * 2;   // global in [0,3072)
                const float* bp; float* Cp; int cl; bool elu;
                if (col < 1024)      { bp = b0 + col;        Cp = C0; cl = col;        elu = true; }
                else if (col < 2048) { bp = b1 + col - 1024; Cp = C1; cl = col - 1024; elu = true; }
                else                 { bp = b2 + col - 2048; Cp = C2; cl = col - 2048; elu = false; }
                float2 bb = *(const float2*)bp;
                float v0 = acc[mt][nt][0] + bb.x, v1 = acc[mt][nt][1] + bb.y;
                float v2 = acc[mt][nt][2] + bb.x, v3 = acc[mt][nt][3] + bb.y;
                if (elu) {
                    v0 = (v0 > 0.f) ? (v0 + 1.f) : expf(v0);
                    v1 = (v1 > 0.f) ? (v1 + 1.f) : expf(v1);
                    v2 = (v2 > 0.f) ? (v2 + 1.f) : expf(v2);
                    v3 = (v3 > 0.f) ? (v3 + 1.f) : expf(v3);
                }
                *(float2*)(Cp + (size_t)r0 * 1024 + cl)       = make_float2(v0, v1);
                *(float2*)(Cp + (size_t)(r0 + 8) * 1024 + cl) = make_float2(v2, v3);
            }
        }
    } else {  // EPI == 2
        #pragma unroll
        for (int mt = 0; mt < 4; mt++) {
            int r0 = m0 + warp_m + mt * 16 + gid;
            #pragma unroll
            for (int nt = 0; nt < 8; nt++) {
                int col = n0 + warp_n + nt * 8 + tig * 2;
                float2 bb = *(const float2*)(b0 + col);
                float v0 = acc[mt][nt][0] + bb.x, v1 = acc[mt][nt][1] + bb.y;
                float v2 = acc[mt][nt][2] + bb.x, v3 = acc[mt][nt][3] + bb.y;
                size_t o0 = (size_t)r0 * Nout + col;
                size_t o1 = (size_t)(r0 + 8) * Nout + col;
                float2 ra = *(const float2*)(Rres + o0);
                float2 rb = *(const float2*)(Rres + o1);
                v0 += ra.x; v1 += ra.y; v2 += rb.x; v3 += rb.y;
                *(float2*)(C0 + o0) = make_float2(v0, v1);
                *(float2*)(C0 + o1) = make_float2(v2, v3);
            }
        }
    }
}

// ---------------- kv = K^T V per (b,h), split over S ----------------
__global__ __launch_bounds__(256) void kv_partial_k(const float* __restrict__ Kp,
                                                    const float* __restrict__ Vp,
                                                    float* __restrict__ kvp)
{
    int bh = blockIdx.x, spi = blockIdx.y;
    int b = bh >> 4, h = bh & 15;
    int tid = threadIdx.x;
    __shared__ float ks[32][64], vs[32][64];
    float acc[4][4] = {};
    int d0 = (tid >> 4) * 4, e0 = (tid & 15) * 4;
    size_t base = ((size_t)b * 4096) * DM + h * 64;
    for (int s0 = spi * 512; s0 < spi * 512 + 512; s0 += 32) {
        #pragma unroll
        for (int i = 0; i < 2; i++) {
            int f = tid + i * 256;
            int r = f >> 4, c = (f & 15) * 4;
            size_t off = base + (size_t)(s0 + r) * DM + c;
            *(float4*)&ks[r][c] = *(const float4*)(Kp + off);
            *(float4*)&vs[r][c] = *(const float4*)(Vp + off);
        }
        __syncthreads();
        #pragma unroll
        for (int ssm = 0; ssm < 32; ssm++) {
            float kd[4] = { ks[ssm][d0], ks[ssm][d0+1], ks[ssm][d0+2], ks[ssm][d0+3] };
            float ve[4] = { vs[ssm][e0], vs[ssm][e0+1], vs[ssm][e0+2], vs[ssm][e0+3] };
            #pragma unroll
            for (int i = 0; i < 4; i++)
                #pragma unroll
                for (int j = 0; j < 4; j++) acc[i][j] += kd[i] * ve[j];
        }
        __syncthreads();
    }
    float* outp = kvp + ((size_t)spi * 64 + bh) * 4096;
    #pragma unroll
    for (int i = 0; i < 4; i++)
        *(float4*)(outp + (d0 + i) * 64 + e0) = make_float4(acc[i][0], acc[i][1], acc[i][2], acc[i][3]);
}

__global__ __launch_bounds__(256) void kv_reduce_k(const float* __restrict__ kvp,
                                                   float* __restrict__ kv)
{
    int i = blockIdx.x * 256 + threadIdx.x;
    float s = 0.f;
    #pragma unroll
    for (int spi = 0; spi < 8; spi++) s += kvp[(size_t)spi * 262144 + i];
    kv[i] = s;
}

// ---------------- attn = q @ kv per (b,h), out -> fp16 ----------------
__global__ __launch_bounds__(256) void attn_k(const float* __restrict__ Q,
                                              const float* __restrict__ KV,
                                              __half* __restrict__ Oh)
{
    int bh = blockIdx.x, st = blockIdx.y;
    int b = bh >> 4, h = bh & 15;
    int tid = threadIdx.x;
    __shared__ float kvs[64][64], qs[64][68];
    const float* kvsrc = KV + (size_t)bh * 4096;
    #pragma unroll
    for (int i = 0; i < 4; i++) {
        int f = tid + i * 256;
        int r = f >> 4, c = (f & 15) * 4;
        *(float4*)&kvs[r][c] = *(const float4*)(kvsrc + r * 64 + c);
    }
    size_t qbase = ((size_t)b * 4096 + st * 64) * DM + h * 64;
    #pragma unroll
    for (int i = 0; i < 4; i++) {
        int f = tid + i * 256;
        int r = f >> 4, c = (f & 15) * 4;
        *(float4*)&qs[r][c] = *(const float4*)(Q + qbase + (size_t)r * DM + c);
    }
    __syncthreads();
    int r = tid >> 2, e0 = (tid & 3) * 16;
    float acc[16] = {};
    #pragma unroll 8
    for (int d = 0; d < 64; d++) {
        float qd = qs[r][d];
        #pragma unroll
        for (int j = 0; j < 16; j++) acc[j] += qd * kvs[d][e0 + j];
    }
    size_t obase = qbase + (size_t)r * DM + e0;
    #pragma unroll
    for (int j = 0; j < 16; j += 2)
        *(uint32_t*)(Oh + obase + j) = packh(acc[j], acc[j + 1]);
}

// ---------------- launch ----------------
extern "C" void kernel_launch(void* const* d_in, const int* in_sizes, int n_in,
                              void* d_out, int out_size)
{
    const float* x   = (const float*)d_in[0];
    const float* wq  = (const float*)d_in[1];
    const float* bq  = (const float*)d_in[2];
    const float* wk  = (const float*)d_in[3];
    const float* bk  = (const float*)d_in[4];
    const float* wv  = (const float*)d_in[5];
    const float* bv  = (const float*)d_in[6];
    const float* wo  = (const float*)d_in[7];
    const float* bo  = (const float*)d_in[8];
    const float* w1  = (const float*)d_in[9];
    const float* b1  = (const float*)d_in[10];
    const float* w2  = (const float*)d_in[11];
    const float* b2  = (const float*)d_in[12];
    const float* g1  = (const float*)d_in[13];
    const float* be1 = (const float*)d_in[14];
    const float* g2  = (const float*)d_in[15];
    const float* be2 = (const float*)d_in[16];
    float* out = (float*)d_out;

    void* sp = nullptr;
    cudaGetSymbolAddress(&sp, g_scratch);
    unsigned char* S = (unsigned char*)sp;
    float* Qb    = (float*)(S + Q_OFF);
    float* Kb    = (float*)(S + K_OFF);
    float* Vb    = (float*)(S + V_OFF);
    float* X1    = (float*)(S + X1_OFF);
    __half* HH   = (__half*)(S + HH_OFF);
    __half* AH   = (__half*)(S + AH_OFF);
    __half* GH   = (__half*)(S + GH_OFF);
    float* KVb   = (float*)(S + KV_OFF);
    float* KVP   = (float*)(S + KVP_OFF);
    __half* WQKV = (__half*)(S + WQKV_OFF);
    __half* WO2  = (__half*)(S + WO2_OFF);
    __half* W1_  = (__half*)(S + W1_OFF);
    __half* W2_  = (__half*)(S + W2_OFF);

    static bool attr_done = false;
    if (!attr_done) {
        cudaFuncSetAttribute(gemm_mma<2>, cudaFuncAttributeMaxDynamicSharedMemorySize, SMEM_GEMM);
        cudaFuncSetAttribute(gemm_mma<3>, cudaFuncAttributeMaxDynamicSharedMemorySize, SMEM_GEMM);
        cudaFuncSetAttribute(gemm_mma<4>, cudaFuncAttributeMaxDynamicSharedMemorySize, SMEM_GEMM);
        attr_done = true;
    }

    dim3 wb(32, 8);
    wsplit_k<<<dim3(32, 32), wb>>>(wq, WQKV,               DM, DM);
    wsplit_k<<<dim3(32, 32), wb>>>(wk, WQKV + 1024 * 1024, DM, DM);
    wsplit_k<<<dim3(32, 32), wb>>>(wv, WQKV + 2048 * 1024, DM, DM);
    wsplit_k<<<dim3(32, 32), wb>>>(wo, WO2, DM, DM);
    wsplit_pack_k<<<dim3(256, 32), wb>>>(w1, W1_, DM, 2 * DFF_);
    wsplit_k<<<dim3(32, 128), wb>>>(w2, W2_, DFF_, DM);

    dim3 gQKV(12, 128), gN1024(4, 128), gFF1(32, 128);

    // LN1
    ln_k<<<M_TOT, 256>>>(x, g1, be1, HH);
    // fused q/k/v projection (elu+1 on q,k)
    gemm_mma<4><<<gQKV, 256, SMEM_GEMM>>>(HH, WQKV, bq, bk, bv, nullptr,
                                          Qb, Kb, Vb, nullptr, DM, 1024);
    // linear attention
    kv_partial_k<<<dim3(64, 8), 256>>>(Kb, Vb, KVP);
    kv_reduce_k<<<1024, 256>>>(KVP, KVb);
    attn_k<<<dim3(64, 64), 256>>>(Qb, KVb, AH);
    // out proj + residual(x)
    gemm_mma<2><<<gN1024, 256, SMEM_GEMM>>>(AH, WO2, bo, nullptr, nullptr, x,
                                            X1, nullptr, nullptr, nullptr, DM, DM);
    // LN2
    ln_k<<<M_TOT, 256>>>(X1, g2, be2, HH);
    // FF1 + fused GEGLU -> fp16
    gemm_mma<3><<<gFF1, 256, SMEM_GEMM>>>(HH, W1_, b1, nullptr, nullptr, nullptr,
                                          nullptr, nullptr, nullptr, GH, DM, DFF_);
    // FF2 + residual(X1)
    gemm_mma<2><<<gN1024, 256, SMEM_GEMM>>>(GH, W2_, b2, nullptr, nullptr, X1,
                                            out, nullptr, nullptr, nullptr, DFF_, DM);
}